// round 5
// baseline (speedup 1.0000x reference)
#include <cuda_runtime.h>
#include <cuda_bf16.h>
#include <math.h>
#include <stdint.h>

#define B_  2
#define T_  1024
#define C_  2048
#define NH  16
#define KH  4
#define H_  128
#define M_  (B_*T_)
#define KV  (KH*H_)     // 512

// fp32 scratch
__device__ float g_q[M_ * C_];
__device__ float g_k[M_ * KV];
// bf16 split scratch
__device__ __nv_bfloat16 g_xh[M_*C_],  g_xl[M_*C_];
__device__ __nv_bfloat16 g_wqh[C_*C_], g_wql[C_*C_];
__device__ __nv_bfloat16 g_wkh[C_*KV], g_wkl[C_*KV];
__device__ __nv_bfloat16 g_wvh[C_*KV], g_wvl[C_*KV];
__device__ __nv_bfloat16 g_woh[C_*C_], g_wol[C_*C_];
__device__ __nv_bfloat16 g_qh[M_*C_],  g_ql[M_*C_];
__device__ __nv_bfloat16 g_kh[M_*KV],  g_kl[M_*KV];
__device__ __nv_bfloat16 g_vh[M_*KV],  g_vl[M_*KV];
__device__ __nv_bfloat16 g_eh[M_*C_],  g_el[M_*C_];

// ---------------- helpers ----------------
__device__ __forceinline__ void ldsm_x4(uint32_t& r0, uint32_t& r1, uint32_t& r2,
                                        uint32_t& r3, uint32_t addr) {
    asm volatile("ldmatrix.sync.aligned.m8n8.x4.shared.b16 {%0,%1,%2,%3}, [%4];"
                 : "=r"(r0), "=r"(r1), "=r"(r2), "=r"(r3) : "r"(addr));
}
__device__ __forceinline__ void ldsm_x2(uint32_t& r0, uint32_t& r1, uint32_t addr) {
    asm volatile("ldmatrix.sync.aligned.m8n8.x2.shared.b16 {%0,%1}, [%2];"
                 : "=r"(r0), "=r"(r1) : "r"(addr));
}
__device__ __forceinline__ void ldsm_x2t(uint32_t& r0, uint32_t& r1, uint32_t addr) {
    asm volatile("ldmatrix.sync.aligned.m8n8.x2.trans.shared.b16 {%0,%1}, [%2];"
                 : "=r"(r0), "=r"(r1) : "r"(addr));
}
__device__ __forceinline__ void mma16816(float* c, const uint32_t* a, const uint32_t* b) {
    asm volatile("mma.sync.aligned.m16n8k16.row.col.f32.bf16.bf16.f32 "
                 "{%0,%1,%2,%3}, {%4,%5,%6,%7}, {%8,%9}, {%0,%1,%2,%3};"
                 : "+f"(c[0]), "+f"(c[1]), "+f"(c[2]), "+f"(c[3])
                 : "r"(a[0]), "r"(a[1]), "r"(a[2]), "r"(a[3]), "r"(b[0]), "r"(b[1]));
}
__device__ __forceinline__ uint32_t pack_bf2(__nv_bfloat16 a, __nv_bfloat16 b) {
    __nv_bfloat162 t = __halves2bfloat162(a, b);
    return *reinterpret_cast<uint32_t*>(&t);
}
__device__ __forceinline__ uint32_t pack_hi2(float x, float y) {
    return pack_bf2(__float2bfloat16(x), __float2bfloat16(y));
}
__device__ __forceinline__ uint32_t pack_lo2(float x, float y) {
    __nv_bfloat16 hx = __float2bfloat16(x), hy = __float2bfloat16(y);
    return pack_bf2(__float2bfloat16(x - __bfloat162float(hx)),
                    __float2bfloat16(y - __bfloat162float(hy)));
}
__device__ __forceinline__ void split_store(float4 v, __nv_bfloat16* hi, __nv_bfloat16* lo) {
    *(uint2*)hi = make_uint2(pack_hi2(v.x, v.y), pack_hi2(v.z, v.w));
    *(uint2*)lo = make_uint2(pack_lo2(v.x, v.y), pack_lo2(v.z, v.w));
}
__device__ __forceinline__ void cp16(uint32_t s, const void* g) {
    asm volatile("cp.async.cg.shared.global [%0], [%1], 16;" :: "r"(s), "l"(g));
}
__device__ __forceinline__ void cp_commit() { asm volatile("cp.async.commit_group;"); }
template<int N> __device__ __forceinline__ void cp_wait() {
    asm volatile("cp.async.wait_group %0;" :: "n"(N));
}

// ---------------------------------------------------------------------------
// Elementwise fp32 -> (hi,lo) bf16 split
// ---------------------------------------------------------------------------
__global__ void split_arr(const float* __restrict__ in, __nv_bfloat16* __restrict__ hi,
                          __nv_bfloat16* __restrict__ lo, int n4) {
    int i = blockIdx.x * blockDim.x + threadIdx.x;
    if (i < n4) {
        float4 v = ((const float4*)in)[i];
        split_store(v, hi + (size_t)i * 4, lo + (size_t)i * 4);
    }
}

// ---------------------------------------------------------------------------
// bf16x3 tensor-core GEMM with pre-split inputs + cp.async 2-stage pipeline.
// Tile 128x128x32, 512 threads.
// ---------------------------------------------------------------------------
#define GA_ST 40
#define GB_ST 136
#define GA_SZ (128*GA_ST)   // 5120 elems
#define GB_SZ (32*GB_ST)    // 4352 elems
#define GA_OFF(st,c) ((st)*2*GA_SZ + (c)*GA_SZ)
#define GB_OFF(st,c) (4*GA_SZ + (st)*2*GB_SZ + (c)*GB_SZ)
#define GEMM_SMEM ((4*GA_SZ + 4*GB_SZ) * 2)   // 75776 bytes

template<int OUTMODE>   // 0: fp32 C, 1: split bf16 (Ch, Cl)
__device__ __forceinline__ void gemm_body(
    const __nv_bfloat16* __restrict__ Ah, const __nv_bfloat16* __restrict__ Al,
    const __nv_bfloat16* __restrict__ Bh, const __nv_bfloat16* __restrict__ Bl,
    float* __restrict__ Cf, __nv_bfloat16* __restrict__ Ch, __nv_bfloat16* __restrict__ Cl,
    int N, int K, int bm0, int bn0)
{
    extern __shared__ __nv_bfloat16 sm[];
    const uint32_t smB = (uint32_t)__cvta_generic_to_shared(sm);

    const int tid = threadIdx.x;
    const int lane = tid & 31;
    const int warp = tid >> 5;
    const int wm = (warp >> 2) * 32;
    const int wn = (warp & 3) * 32;

    // producer chunk indices (16B = 8 bf16 per cp.async)
    const int ar = tid >> 2, ac = (tid & 3) * 8;    // A: 128 rows x 4 chunks
    const int br = tid >> 4, bc = (tid & 15) * 8;   // B: 32 rows x 16 chunks

    const int KT = K / 32;

    auto issue = [&](int st, int k0) {
        cp16(smB + (uint32_t)(GA_OFF(st,0) + ar * GA_ST + ac) * 2,
             Ah + (size_t)(bm0 + ar) * K + k0 + ac);
        cp16(smB + (uint32_t)(GA_OFF(st,1) + ar * GA_ST + ac) * 2,
             Al + (size_t)(bm0 + ar) * K + k0 + ac);
        cp16(smB + (uint32_t)(GB_OFF(st,0) + br * GB_ST + bc) * 2,
             Bh + (size_t)(k0 + br) * N + bn0 + bc);
        cp16(smB + (uint32_t)(GB_OFF(st,1) + br * GB_ST + bc) * 2,
             Bl + (size_t)(k0 + br) * N + bn0 + bc);
        cp_commit();
    };

    float acc[2][4][4];
    #pragma unroll
    for (int i = 0; i < 2; i++)
        #pragma unroll
        for (int j = 0; j < 4; j++)
            #pragma unroll
            for (int u = 0; u < 4; u++) acc[i][j][u] = 0.f;

    issue(0, 0);
    issue(1, 32);

    for (int kt = 0; kt < KT; kt++) {
        if (kt == KT - 1) cp_wait<0>(); else cp_wait<1>();
        __syncthreads();

        const int st = kt & 1;
        #pragma unroll
        for (int ks = 0; ks < 32; ks += 16) {
            uint32_t ah[2][4], al[2][4], bh[4][2], bl[4][2];
            const int arow = (lane & 15);
            const int acol = ks + ((lane >> 4) << 3);
            #pragma unroll
            for (int i = 0; i < 2; i++) {
                uint32_t offh = (uint32_t)(GA_OFF(st,0) + (wm + i*16 + arow) * GA_ST + acol) * 2;
                uint32_t offl = (uint32_t)(GA_OFF(st,1) + (wm + i*16 + arow) * GA_ST + acol) * 2;
                ldsm_x4(ah[i][0], ah[i][1], ah[i][2], ah[i][3], smB + offh);
                ldsm_x4(al[i][0], al[i][1], al[i][2], al[i][3], smB + offl);
            }
            const int brow = ks + (lane & 15);
            #pragma unroll
            for (int j = 0; j < 4; j++) {
                uint32_t offh = (uint32_t)(GB_OFF(st,0) + brow * GB_ST + wn + j*8) * 2;
                uint32_t offl = (uint32_t)(GB_OFF(st,1) + brow * GB_ST + wn + j*8) * 2;
                ldsm_x2t(bh[j][0], bh[j][1], smB + offh);
                ldsm_x2t(bl[j][0], bl[j][1], smB + offl);
            }
            #pragma unroll
            for (int i = 0; i < 2; i++)
                #pragma unroll
                for (int j = 0; j < 4; j++) {
                    mma16816(acc[i][j], ah[i], bh[j]);
                    mma16816(acc[i][j], al[i], bh[j]);
                    mma16816(acc[i][j], ah[i], bl[j]);
                }
        }
        __syncthreads();
        if (kt + 2 < KT) issue(st, (kt + 2) * 32);
    }

    const int g = lane >> 2, tg = lane & 3;
    #pragma unroll
    for (int i = 0; i < 2; i++)
        #pragma unroll
        for (int j = 0; j < 4; j++) {
            int r0 = bm0 + wm + i*16 + g;
            int c0 = bn0 + wn + j*8 + tg*2;
            if (OUTMODE == 0) {
                *(float2*)&Cf[(size_t)r0 * N + c0]     = make_float2(acc[i][j][0], acc[i][j][1]);
                *(float2*)&Cf[(size_t)(r0+8) * N + c0] = make_float2(acc[i][j][2], acc[i][j][3]);
            } else {
                *(uint32_t*)&Ch[(size_t)r0 * N + c0]     = pack_hi2(acc[i][j][0], acc[i][j][1]);
                *(uint32_t*)&Cl[(size_t)r0 * N + c0]     = pack_lo2(acc[i][j][0], acc[i][j][1]);
                *(uint32_t*)&Ch[(size_t)(r0+8) * N + c0] = pack_hi2(acc[i][j][2], acc[i][j][3]);
                *(uint32_t*)&Cl[(size_t)(r0+8) * N + c0] = pack_lo2(acc[i][j][2], acc[i][j][3]);
            }
        }
}

__global__ __launch_bounds__(512, 1) void gemm_f32(
    const __nv_bfloat16* __restrict__ Ah, const __nv_bfloat16* __restrict__ Al,
    const __nv_bfloat16* __restrict__ Bh, const __nv_bfloat16* __restrict__ Bl,
    float* __restrict__ C, int N, int K)
{
    gemm_body<0>(Ah, Al, Bh, Bl, C, nullptr, nullptr, N, K, blockIdx.y * 128, blockIdx.x * 128);
}

// K-proj (fp32 out) and V-proj (split bf16 out) fused over blockIdx.z
__global__ __launch_bounds__(512, 1) void gemm_kv(
    const __nv_bfloat16* __restrict__ xh, const __nv_bfloat16* __restrict__ xl,
    const __nv_bfloat16* __restrict__ wkh, const __nv_bfloat16* __restrict__ wkl,
    const __nv_bfloat16* __restrict__ wvh, const __nv_bfloat16* __restrict__ wvl,
    float* __restrict__ ck, __nv_bfloat16* __restrict__ cvh, __nv_bfloat16* __restrict__ cvl)
{
    if (blockIdx.z == 0)
        gemm_body<0>(xh, xl, wkh, wkl, ck, nullptr, nullptr, KV, C_, blockIdx.y * 128, blockIdx.x * 128);
    else
        gemm_body<1>(xh, xl, wvh, wvl, nullptr, cvh, cvl, KV, C_, blockIdx.y * 128, blockIdx.x * 128);
}

// ---------------------------------------------------------------------------
// Fused RMSNorm + RoPE; reads fp32, writes split bf16.
// ---------------------------------------------------------------------------
__global__ void rmsrope_kernel(const float* __restrict__ buf,
                               __nv_bfloat16* __restrict__ oh, __nv_bfloat16* __restrict__ ol,
                               int D, float scale) {
    __shared__ float s_x[2048];
    __shared__ float s_wred[8];

    const int row = blockIdx.x;
    const int t = row % T_;
    const int tid = threadIdx.x;
    const int lane = tid & 31;
    const int warp = tid >> 5;
    const float* rp = buf + (size_t)row * D;

    float ss = 0.f;
    for (int d = tid; d < D; d += 256) {
        float v = rp[d];
        s_x[d] = v;
        ss = fmaf(v, v, ss);
    }
    #pragma unroll
    for (int off = 16; off > 0; off >>= 1)
        ss += __shfl_xor_sync(0xffffffffu, ss, off);
    if (lane == 0) s_wred[warp] = ss;
    __syncthreads();
    float tot = 0.f;
    #pragma unroll
    for (int w = 0; w < 8; w++) tot += s_wred[w];
    const float inv = rsqrtf(tot / (float)D + 1e-6f) * scale;

    for (int d = tid; d < D; d += 256) {
        int h = d & 127;
        int i = h & 63;
        float fraction = (float)i * (1.0f / 64.0f);
        float inv_freq = powf(10000.0f, -fraction);
        float ang = (float)t * inv_freq;
        float sv = sinf(ang), cv = cosf(ang);
        float xn = s_x[d] * inv;
        float partner = (h < 64) ? s_x[d + 64] : s_x[d - 64];
        partner *= inv;
        float val = (h < 64) ? fmaf(xn, cv, -partner * sv)
                             : fmaf(xn, cv,  partner * sv);
        __nv_bfloat16 hh = __float2bfloat16(val);
        oh[(size_t)row * D + d] = hh;
        ol[(size_t)row * D + d] = __float2bfloat16(val - __bfloat162float(hh));
    }
}

// ---------------------------------------------------------------------------
// Tensor-core flash attention, pre-split bf16 inputs, cp.async 2-stage KV.
// Block = (128 q rows, head, batch), 256 threads.
// ---------------------------------------------------------------------------
#define BQ 128
#define BK 64
#define QS 136

#define AQ_H 0
#define AQ_L (BQ*QS)                 // 17408
#define AKV_BASE (2*BQ*QS)           // 34816
#define AKV_STG (4*BK*QS)            // 34816 elems per stage
#define AK_H(st) (AKV_BASE + (st)*AKV_STG)
#define AK_L(st) (AK_H(st) + BK*QS)
#define AV_H(st) (AK_H(st) + 2*BK*QS)
#define AV_L(st) (AK_H(st) + 3*BK*QS)
#define ATTN_SMEM ((AKV_BASE + 2*AKV_STG) * 2)   // 208896 bytes

__global__ __launch_bounds__(256, 1) void attn_mma(
    const __nv_bfloat16* __restrict__ qhp, const __nv_bfloat16* __restrict__ qlp,
    const __nv_bfloat16* __restrict__ khp, const __nv_bfloat16* __restrict__ klp,
    const __nv_bfloat16* __restrict__ vhp, const __nv_bfloat16* __restrict__ vlp,
    __nv_bfloat16* __restrict__ ehp, __nv_bfloat16* __restrict__ elp)
{
    extern __shared__ __nv_bfloat16 sm[];
    const uint32_t smB = (uint32_t)__cvta_generic_to_shared(sm);
    const int tid = threadIdx.x;
    const int lane = tid & 31;
    const int warp = tid >> 5;
    const int b = blockIdx.z;
    const int n = blockIdx.y;
    const int khead = n >> 2;
    const int t0 = blockIdx.x * BQ;

    // Q chunks: per comp 128 rows x 16 chunks
    auto issueQ = [&]() {
        #pragma unroll
        for (int j = 0; j < 8; j++) {
            int i = tid + j * 256;
            int row = i >> 4, c = (i & 15) * 8;
            size_t goff = ((size_t)(b * T_ + t0 + row) * C_) + n * H_ + c;
            cp16(smB + (uint32_t)(AQ_H + row * QS + c) * 2, qhp + goff);
            cp16(smB + (uint32_t)(AQ_L + row * QS + c) * 2, qlp + goff);
        }
    };
    // KV chunks: per comp 64 rows x 16 chunks
    auto issueKV = [&](int st, int s0) {
        #pragma unroll
        for (int j = 0; j < 4; j++) {
            int i = tid + j * 256;
            int row = i >> 4, c = (i & 15) * 8;
            size_t goff = ((size_t)(b * T_ + s0 + row) * KV) + khead * H_ + c;
            cp16(smB + (uint32_t)(AK_H(st) + row * QS + c) * 2, khp + goff);
            cp16(smB + (uint32_t)(AK_L(st) + row * QS + c) * 2, klp + goff);
            cp16(smB + (uint32_t)(AV_H(st) + row * QS + c) * 2, vhp + goff);
            cp16(smB + (uint32_t)(AV_L(st) + row * QS + c) * 2, vlp + goff);
        }
        cp_commit();
    };

    issueQ();
    issueKV(0, 0);        // group 0 (Q + KV0)
    issueKV(1, BK);       // group 1

    const int g = lane >> 2, tg = lane & 3;
    float m0 = -INFINITY, m1 = -INFINITY, l0 = 0.f, l1 = 0.f;
    float o[16][4];
    #pragma unroll
    for (int nn = 0; nn < 16; nn++)
        #pragma unroll
        for (int u = 0; u < 4; u++) o[nn][u] = 0.f;

    const int NT = T_ / BK;   // 16
    for (int stile = 0; stile < NT; stile++) {
        if (stile == NT - 1) cp_wait<0>(); else cp_wait<1>();
        __syncthreads();
        const int st = stile & 1;

        // ---- S = Q @ K^T ----
        float s[8][4];
        #pragma unroll
        for (int j = 0; j < 8; j++)
            #pragma unroll
            for (int u = 0; u < 4; u++) s[j][u] = 0.f;

        #pragma unroll
        for (int ks = 0; ks < 8; ks++) {
            uint32_t qh[4], ql[4];
            uint32_t qrow = (uint32_t)(warp * 16 + (lane & 15));
            uint32_t qcol = (uint32_t)(ks * 16 + ((lane >> 4) << 3));
            ldsm_x4(qh[0], qh[1], qh[2], qh[3], smB + (uint32_t)(AQ_H + qrow * QS + qcol) * 2);
            ldsm_x4(ql[0], ql[1], ql[2], ql[3], smB + (uint32_t)(AQ_L + qrow * QS + qcol) * 2);
            #pragma unroll
            for (int j = 0; j < 8; j++) {
                uint32_t kh2[2], kl2[2];
                uint32_t krow = (uint32_t)(j * 8 + (lane & 7));
                uint32_t kcol = (uint32_t)(ks * 16 + (((lane & 15) >> 3) << 3));
                ldsm_x2(kh2[0], kh2[1], smB + (uint32_t)(AK_H(st) + krow * QS + kcol) * 2);
                ldsm_x2(kl2[0], kl2[1], smB + (uint32_t)(AK_L(st) + krow * QS + kcol) * 2);
                mma16816(s[j], qh, kh2);
                mma16816(s[j], ql, kh2);
                mma16816(s[j], qh, kl2);
            }
        }

        // ---- online softmax ----
        float mx0 = -INFINITY, mx1 = -INFINITY;
        #pragma unroll
        for (int j = 0; j < 8; j++) {
            mx0 = fmaxf(mx0, fmaxf(s[j][0], s[j][1]));
            mx1 = fmaxf(mx1, fmaxf(s[j][2], s[j][3]));
        }
        mx0 = fmaxf(mx0, __shfl_xor_sync(0xffffffffu, mx0, 1));
        mx0 = fmaxf(mx0, __shfl_xor_sync(0xffffffffu, mx0, 2));
        mx1 = fmaxf(mx1, __shfl_xor_sync(0xffffffffu, mx1, 1));
        mx1 = fmaxf(mx1, __shfl_xor_sync(0xffffffffu, mx1, 2));
        float m0n = fmaxf(m0, mx0);
        float m1n = fmaxf(m1, mx1);
        float a0 = __expf(m0 - m0n);
        float a1 = __expf(m1 - m1n);
        float sum0 = 0.f, sum1 = 0.f;
        #pragma unroll
        for (int j = 0; j < 8; j++) {
            s[j][0] = __expf(s[j][0] - m0n);
            s[j][1] = __expf(s[j][1] - m0n);
            s[j][2] = __expf(s[j][2] - m1n);
            s[j][3] = __expf(s[j][3] - m1n);
            sum0 += s[j][0] + s[j][1];
            sum1 += s[j][2] + s[j][3];
        }
        sum0 += __shfl_xor_sync(0xffffffffu, sum0, 1);
        sum0 += __shfl_xor_sync(0xffffffffu, sum0, 2);
        sum1 += __shfl_xor_sync(0xffffffffu, sum1, 1);
        sum1 += __shfl_xor_sync(0xffffffffu, sum1, 2);
        l0 = l0 * a0 + sum0;
        l1 = l1 * a1 + sum1;
        m0 = m0n; m1 = m1n;
        #pragma unroll
        for (int nn = 0; nn < 16; nn++) {
            o[nn][0] *= a0; o[nn][1] *= a0;
            o[nn][2] *= a1; o[nn][3] *= a1;
        }

        // ---- O += P @ V ----
        #pragma unroll
        for (int kk = 0; kk < 4; kk++) {
            const int j0 = kk * 2;
            uint32_t ah[4], al[4];
            ah[0] = pack_hi2(s[j0][0],   s[j0][1]);
            ah[1] = pack_hi2(s[j0][2],   s[j0][3]);
            ah[2] = pack_hi2(s[j0+1][0], s[j0+1][1]);
            ah[3] = pack_hi2(s[j0+1][2], s[j0+1][3]);
            al[0] = pack_lo2(s[j0][0],   s[j0][1]);
            al[1] = pack_lo2(s[j0][2],   s[j0][3]);
            al[2] = pack_lo2(s[j0+1][0], s[j0+1][1]);
            al[3] = pack_lo2(s[j0+1][2], s[j0+1][3]);
            #pragma unroll
            for (int nn = 0; nn < 16; nn++) {
                uint32_t bh2[2], bl2[2];
                uint32_t vrow = (uint32_t)(kk * 16 + (lane & 15));
                ldsm_x2t(bh2[0], bh2[1], smB + (uint32_t)(AV_H(st) + vrow * QS + nn * 8) * 2);
                ldsm_x2t(bl2[0], bl2[1], smB + (uint32_t)(AV_L(st) + vrow * QS + nn * 8) * 2);
                mma16816(o[nn], ah, bh2);
                mma16816(o[nn], al, bh2);
                mma16816(o[nn], ah, bl2);
            }
        }

        __syncthreads();
        if (stile + 2 < NT) issueKV(st, (stile + 2) * BK);
    }

    // ---- epilogue: normalize, split to bf16, write ----
    float il0 = 1.0f / l0;
    float il1 = 1.0f / l1;
    const int r0 = t0 + warp * 16 + g;
    #pragma unroll
    for (int nn = 0; nn < 16; nn++) {
        int c0 = nn * 8 + tg * 2;
        size_t base0 = ((size_t)(b * T_ + r0) * C_) + n * H_ + c0;
        size_t base1 = ((size_t)(b * T_ + r0 + 8) * C_) + n * H_ + c0;
        float v00 = o[nn][0] * il0, v01 = o[nn][1] * il0;
        float v10 = o[nn][2] * il1, v11 = o[nn][3] * il1;
        *(uint32_t*)&ehp[base0] = pack_hi2(v00, v01);
        *(uint32_t*)&elp[base0] = pack_lo2(v00, v01);
        *(uint32_t*)&ehp[base1] = pack_hi2(v10, v11);
        *(uint32_t*)&elp[base1] = pack_lo2(v10, v11);
    }
}

// ---------------------------------------------------------------------------
extern "C" void kernel_launch(void* const* d_in, const int* in_sizes, int n_in,
                              void* d_out, int out_size) {
    const float* x  = (const float*)d_in[0];
    const float* wq = (const float*)d_in[1];
    const float* wk = (const float*)d_in[2];
    const float* wv = (const float*)d_in[3];
    const float* wo = (const float*)d_in[4];
    float* out = (float*)d_out;

    float *gq, *gk;
    __nv_bfloat16 *xh,*xl,*wqh,*wql,*wkh,*wkl,*wvh,*wvl,*woh,*wol;
    __nv_bfloat16 *qh,*ql,*kh,*kl,*vh,*vl,*eh,*el;
    cudaGetSymbolAddress((void**)&gq, g_q);
    cudaGetSymbolAddress((void**)&gk, g_k);
    cudaGetSymbolAddress((void**)&xh, g_xh);   cudaGetSymbolAddress((void**)&xl, g_xl);
    cudaGetSymbolAddress((void**)&wqh, g_wqh); cudaGetSymbolAddress((void**)&wql, g_wql);
    cudaGetSymbolAddress((void**)&wkh, g_wkh); cudaGetSymbolAddress((void**)&wkl, g_wkl);
    cudaGetSymbolAddress((void**)&wvh, g_wvh); cudaGetSymbolAddress((void**)&wvl, g_wvl);
    cudaGetSymbolAddress((void**)&woh, g_woh); cudaGetSymbolAddress((void**)&wol, g_wol);
    cudaGetSymbolAddress((void**)&qh, g_qh);   cudaGetSymbolAddress((void**)&ql, g_ql);
    cudaGetSymbolAddress((void**)&kh, g_kh);   cudaGetSymbolAddress((void**)&kl, g_kl);
    cudaGetSymbolAddress((void**)&vh, g_vh);   cudaGetSymbolAddress((void**)&vl, g_vl);
    cudaGetSymbolAddress((void**)&eh, g_eh);   cudaGetSymbolAddress((void**)&el, g_el);

    cudaFuncSetAttribute(gemm_f32, cudaFuncAttributeMaxDynamicSharedMemorySize, GEMM_SMEM);
    cudaFuncSetAttribute(gemm_kv,  cudaFuncAttributeMaxDynamicSharedMemorySize, GEMM_SMEM);
    cudaFuncSetAttribute(attn_mma, cudaFuncAttributeMaxDynamicSharedMemorySize, ATTN_SMEM);

    // split inputs
    split_arr<<<(M_*C_/4)/256, 256>>>(x,  xh,  xl,  M_*C_/4);
    split_arr<<<(C_*C_/4)/256, 256>>>(wq, wqh, wql, C_*C_/4);
    split_arr<<<(C_*KV/4)/256, 256>>>(wk, wkh, wkl, C_*KV/4);
    split_arr<<<(C_*KV/4)/256, 256>>>(wv, wvh, wvl, C_*KV/4);
    split_arr<<<(C_*C_/4)/256, 256>>>(wo, woh, wol, C_*C_/4);

    // projections
    gemm_f32<<<dim3(C_/128, M_/128), 512, GEMM_SMEM>>>(xh, xl, wqh, wql, gq, C_, C_);
    gemm_kv<<<dim3(KV/128, M_/128, 2), 512, GEMM_SMEM>>>(xh, xl, wkh, wkl, wvh, wvl, gk, vh, vl);

    // rmsnorm + rope -> split bf16
    const float qscale = 0.08838834764831845f;  // 1/sqrt(128)
    rmsrope_kernel<<<M_, 256>>>(gq, qh, ql, C_, qscale);
    rmsrope_kernel<<<M_, 256>>>(gk, kh, kl, KV, 1.0f);

    // flash attention -> split bf16 enc
    attn_mma<<<dim3(T_/BQ, NH, B_), 256, ATTN_SMEM>>>(qh, ql, kh, kl, vh, vl, eh, el);

    // output projection
    gemm_f32<<<dim3(C_/128, M_/128), 512, GEMM_SMEM>>>(eh, el, woh, wol, out, C_, C_);
}